// round 12
// baseline (speedup 1.0000x reference)
#include <cuda_runtime.h>
#include <cuda_bf16.h>
#include <float.h>
#include <stdint.h>

// ===========================================================================
// TopK SAE — round 10: fix topk register-spill regression (dynamic index ->
// unrolled compare). mma.sync encode + bf16 latents + barrier-free topk.
// Output layout: d_out = [recon (8192*768) | sparse (8192*12288)] fp32
// ===========================================================================

#define N_ROWS 8192
#define DM     768
#define DS     12288
#define KSEL   32
#define NCAND  48

__device__ __nv_bfloat16  g_latents[(size_t)N_ROWS * DS]; // 201 MB approx scores
__device__ __nv_bfloat16  g_xb[(size_t)N_ROWS * DM];      // bf16 x
__device__ __nv_bfloat16  g_wb[(size_t)DS * DM];          // bf16 W_enc
__device__ float          g_wdecT[(size_t)DS * DM];       // W_dec transposed
__device__ int            g_cidx[N_ROWS * NCAND];
__device__ float          g_vals[N_ROWS * KSEL];
__device__ int            g_idx [N_ROWS * KSEL];

__device__ __forceinline__ uint32_t smem_u32(const void* p) {
    return (uint32_t)__cvta_generic_to_shared(p);
}
__device__ __forceinline__ void cp_async16(uint32_t dst, const void* src) {
    asm volatile("cp.async.cg.shared.global [%0], [%1], 16;\n" :: "r"(dst), "l"(src));
}
__device__ __forceinline__ void ldsm_x4(uint32_t& r0, uint32_t& r1,
                                        uint32_t& r2, uint32_t& r3, uint32_t addr) {
    asm volatile("ldmatrix.sync.aligned.m8n8.x4.shared.b16 {%0,%1,%2,%3}, [%4];"
                 : "=r"(r0), "=r"(r1), "=r"(r2), "=r"(r3) : "r"(addr));
}
// monotone map: float bits -> uint32 preserving order
__device__ __forceinline__ uint32_t fmono(float f) {
    uint32_t b = __float_as_uint(f);
    return (b & 0x80000000u) ? ~b : (b | 0x80000000u);
}

// ---------------------------------------------------------------------------
// Kernel 0: fp32 -> bf16 conversion
// ---------------------------------------------------------------------------
__global__ void convert_kernel(const float* __restrict__ src,
                               __nv_bfloat16* __restrict__ dst, int n)
{
    int i = (blockIdx.x * blockDim.x + threadIdx.x) * 4;
    if (i < n) {
        float4 v = *(const float4*)(src + i);
        *(__nv_bfloat162*)(dst + i)     = __floats2bfloat162_rn(v.x, v.y);
        *(__nv_bfloat162*)(dst + i + 2) = __floats2bfloat162_rn(v.z, v.w);
    }
}

// ---------------------------------------------------------------------------
// Kernel 1: bf16 NT-GEMM (mma.sync m16n8k16), CTA tile 128x128, K-chunk 64,
// 2-stage cp.async, 8 warps (4m x 2n), warp tile 32x64. Stores bf16 latents.
// ---------------------------------------------------------------------------
#define MT 128
#define NT 128
#define KT 64
#define NCH (DM / KT)            // 12
#define STG_BYTES (128 * 128)    // 16 KB per operand per stage
#define ENC_SMEM (4 * STG_BYTES) // 64 KB

__device__ __forceinline__ int swzb(int row, int kc) {
    return row * 128 + ((kc ^ (row & 7)) * 16);
}

__global__ __launch_bounds__(256, 2)
void encode_gemm_bf16(const float* __restrict__ b_enc)
{
    extern __shared__ __align__(128) char esm[];
    const uint32_t sb = smem_u32(esm);
    const int tid  = threadIdx.x;
    const int wid  = tid >> 5;
    const int lane = tid & 31;
    const int m0   = blockIdx.y * MT;
    const int n0   = blockIdx.x * NT;
    const int wm   = (wid & 3) * 32;
    const int wn   = (wid >> 2) * 64;

    float acc[2][8][4];
    #pragma unroll
    for (int mt = 0; mt < 2; mt++)
        #pragma unroll
        for (int nt = 0; nt < 8; nt++)
            #pragma unroll
            for (int f = 0; f < 4; f++)
                acc[mt][nt][f] = 0.f;

    auto issue = [&](int st, int kt) {
        const uint32_t Ab = sb + st * STG_BYTES;
        const uint32_t Bb = sb + (2 + st) * STG_BYTES;
        #pragma unroll
        for (int i = 0; i < 4; i++) {
            int u = tid + i * 256;           // 0..1023
            int r = u >> 3, kc = u & 7;
            cp_async16(Ab + swzb(r, kc), g_xb + (size_t)(m0 + r) * DM + kt + kc * 8);
        }
        #pragma unroll
        for (int i = 0; i < 4; i++) {
            int u = tid + i * 256;
            int r = u >> 3, kc = u & 7;
            cp_async16(Bb + swzb(r, kc), g_wb + (size_t)(n0 + r) * DM + kt + kc * 8);
        }
        asm volatile("cp.async.commit_group;\n");
    };

    issue(0, 0);

    for (int it = 0; it < NCH; it++) {
        if (it + 1 < NCH) {
            issue((it + 1) & 1, (it + 1) * KT);
            asm volatile("cp.async.wait_group 1;\n");
        } else {
            asm volatile("cp.async.wait_group 0;\n");
        }
        __syncthreads();

        const uint32_t Ab = sb + (it & 1) * STG_BYTES;
        const uint32_t Bb = sb + (2 + (it & 1)) * STG_BYTES;
        #pragma unroll
        for (int ks = 0; ks < 4; ks++) {          // four k16 steps per chunk
            const int kb = ks * 2;
            uint32_t a[2][4];
            #pragma unroll
            for (int mt = 0; mt < 2; mt++) {
                int row = wm + mt * 16 + (lane & 15);
                int kc  = kb + (lane >> 4);
                ldsm_x4(a[mt][0], a[mt][1], a[mt][2], a[mt][3], Ab + swzb(row, kc));
            }
            uint32_t b[8][2];
            #pragma unroll
            for (int ng = 0; ng < 4; ng++) {
                int row = wn + ng * 16 + (lane & 15);
                int kc  = kb + (lane >> 4);
                uint32_t r0, r1, r2, r3;
                ldsm_x4(r0, r1, r2, r3, Bb + swzb(row, kc));
                b[ng * 2][0]     = r0;
                b[ng * 2 + 1][0] = r1;
                b[ng * 2][1]     = r2;
                b[ng * 2 + 1][1] = r3;
            }
            #pragma unroll
            for (int mt = 0; mt < 2; mt++)
                #pragma unroll
                for (int nt = 0; nt < 8; nt++)
                    asm volatile(
                        "mma.sync.aligned.m16n8k16.row.col.f32.bf16.bf16.f32 "
                        "{%0,%1,%2,%3}, {%4,%5,%6,%7}, {%8,%9}, {%0,%1,%2,%3};"
                        : "+f"(acc[mt][nt][0]), "+f"(acc[mt][nt][1]),
                          "+f"(acc[mt][nt][2]), "+f"(acc[mt][nt][3])
                        : "r"(a[mt][0]), "r"(a[mt][1]), "r"(a[mt][2]), "r"(a[mt][3]),
                          "r"(b[nt][0]), "r"(b[nt][1]));
        }
        __syncthreads();
    }

    // epilogue: + b_enc, store bf16 latents
    #pragma unroll
    for (int mt = 0; mt < 2; mt++) {
        int r0 = m0 + wm + mt * 16 + (lane >> 2);
        #pragma unroll
        for (int nt = 0; nt < 8; nt++) {
            int cg = n0 + wn + nt * 8 + (lane & 3) * 2;
            float2 be = *(const float2*)&b_enc[cg];
            __nv_bfloat162 o0 = __floats2bfloat162_rn(acc[mt][nt][0] + be.x,
                                                      acc[mt][nt][1] + be.y);
            __nv_bfloat162 o1 = __floats2bfloat162_rn(acc[mt][nt][2] + be.x,
                                                      acc[mt][nt][3] + be.y);
            *(__nv_bfloat162*)&g_latents[(size_t)r0 * DS + cg]       = o0;
            *(__nv_bfloat162*)&g_latents[(size_t)(r0 + 8) * DS + cg] = o1;
        }
    }
}

// ---------------------------------------------------------------------------
// Kernel 2: per-row top-48 candidates — barrier-free per-warp selection.
// v[] clear uses UNROLLED COMPARE (compile-time indices) so the array stays
// in registers (dynamic indexing here was the round-7 local-memory spill).
// ---------------------------------------------------------------------------
#define TPR 48

__global__ __launch_bounds__(256)
void topk_cand_kernel()
{
    __shared__ unsigned long long wk[8 * NCAND];   // 3 KB

    const int row  = blockIdx.x;
    const int tid  = threadIdx.x;
    const int w    = tid >> 5;
    const int lane = tid & 31;
    const uint4* lat4 = (const uint4*)(g_latents + (size_t)row * DS); // 1536 chunks

    float v[TPR];
    #pragma unroll
    for (int i = 0; i < 6; i++) {
        uint4 c = lat4[tid + i * 256];
        const __nv_bfloat162* h = (const __nv_bfloat162*)&c;
        #pragma unroll
        for (int e2 = 0; e2 < 4; e2++) {
            float2 f = __bfloat1622float2(h[e2]);
            v[i * 8 + e2 * 2]     = f.x;
            v[i * 8 + e2 * 2 + 1] = f.y;
        }
    }
    // col(j) = tid*8 + (j>>3)*2048 + (j&7)

    float lmax = -FLT_MAX;
    int   lj   = 0;
    #pragma unroll
    for (int j = 0; j < TPR; j++)
        if (v[j] > lmax) { lmax = v[j]; lj = j; }
    unsigned long long lkey =
        ((unsigned long long)fmono(lmax) << 32) |
        (uint32_t)(tid * 8 + (lj >> 3) * 2048 + (lj & 7));

    // Phase 1: per-warp top-48, no block barriers
    for (int it = 0; it < NCAND; it++) {
        unsigned long long k = lkey;
        #pragma unroll
        for (int off = 16; off > 0; off >>= 1) {
            unsigned long long o = __shfl_down_sync(0xffffffffu, k, off);
            if (o > k) k = o;
        }
        k = __shfl_sync(0xffffffffu, k, 0);
        if (lane == 0) wk[w * NCAND + it] = k;
        const uint32_t col = (uint32_t)k;
        if (((col >> 3) & 255) == (uint32_t)tid) {
            const int jw = (int)((col >> 3) >> 8) * 8 + (int)(col & 7);
            #pragma unroll
            for (int jj = 0; jj < TPR; jj++)     // compile-time index: no spill
                if (jj == jw) v[jj] = -FLT_MAX;
            lmax = -FLT_MAX; lj = 0;
            #pragma unroll
            for (int jj = 0; jj < TPR; jj++)
                if (v[jj] > lmax) { lmax = v[jj]; lj = jj; }
            lkey = ((unsigned long long)fmono(lmax) << 32) |
                   (uint32_t)(tid * 8 + (lj >> 3) * 2048 + (lj & 7));
        }
    }
    __syncthreads();

    // Phase 2: warp 0 merges 8x48 = 384 candidates -> global top-48
    if (w == 0) {
        unsigned long long arr[12];
        #pragma unroll
        for (int q = 0; q < 12; q++)
            arr[q] = wk[lane * 12 + q];
        unsigned long long mkey = 0;
        #pragma unroll
        for (int q = 0; q < 12; q++)
            if (arr[q] > mkey) mkey = arr[q];

        for (int it = 0; it < NCAND; it++) {
            unsigned long long k = mkey;
            #pragma unroll
            for (int off = 16; off > 0; off >>= 1) {
                unsigned long long o = __shfl_down_sync(0xffffffffu, k, off);
                if (o > k) k = o;
            }
            k = __shfl_sync(0xffffffffu, k, 0);
            if (lane == 0)
                g_cidx[row * NCAND + it] = (int)(uint32_t)k;
            if (k == mkey) {
                #pragma unroll
                for (int q = 0; q < 12; q++)
                    if (arr[q] == k) arr[q] = 0;
                mkey = 0;
                #pragma unroll
                for (int q = 0; q < 12; q++)
                    if (arr[q] > mkey) mkey = arr[q];
            }
        }
    }
}

// ---------------------------------------------------------------------------
// Kernel 3: exact fp32 refine — 48 candidate dots (float4), exact top-32,
// writes vals/idx AND scatters into sparse (zero runs first).
// ---------------------------------------------------------------------------
__global__ __launch_bounds__(256)
void refine_kernel(const float* __restrict__ x,
                   const float* __restrict__ W_enc,
                   const float* __restrict__ b_enc,
                   float* __restrict__ sparse)
{
    __shared__ float4 xr4[DM / 4];
    __shared__ float  cv[NCAND];
    __shared__ int    ci[NCAND];

    const int row  = blockIdx.x;
    const int tid  = threadIdx.x;
    const int wid  = tid >> 5;
    const int lane = tid & 31;

    if (tid < DM / 4)
        xr4[tid] = ((const float4*)(x + (size_t)row * DM))[tid];
    if (tid < NCAND)
        ci[tid] = g_cidx[row * NCAND + tid];
    __syncthreads();

    for (int j = wid; j < NCAND; j += 8) {
        const int idx = ci[j];
        const float4* wr4 = (const float4*)(W_enc + (size_t)idx * DM);
        float s = 0.f;
        #pragma unroll
        for (int q = 0; q < 6; q++) {
            float4 a = xr4[lane + 32 * q];
            float4 b = wr4[lane + 32 * q];
            s += a.x * b.x + a.y * b.y + a.z * b.z + a.w * b.w;
        }
        #pragma unroll
        for (int off = 16; off > 0; off >>= 1)
            s += __shfl_down_sync(0xffffffffu, s, off);
        if (lane == 0) cv[j] = s + b_enc[idx];
    }
    __syncthreads();

    if (wid == 0) {
        float v0 = cv[lane];
        float v1 = (lane < NCAND - 32) ? cv[lane + 32] : -FLT_MAX;
        const int i0 = lane, i1 = lane + 32;
        for (int it = 0; it < KSEL; it++) {
            float m = v0; int mi = i0;
            if (v1 > m) { m = v1; mi = i1; }
            float wv = m; int wg = mi;
            #pragma unroll
            for (int off = 16; off > 0; off >>= 1) {
                float ov = __shfl_down_sync(0xffffffffu, wv, off);
                int   og = __shfl_down_sync(0xffffffffu, wg, off);
                if (ov > wv) { wv = ov; wg = og; }
            }
            wv = __shfl_sync(0xffffffffu, wv, 0);
            wg = __shfl_sync(0xffffffffu, wg, 0);
            if (lane == 0) {
                const int gi = ci[wg];
                g_vals[row * KSEL + it] = wv;
                g_idx [row * KSEL + it] = gi;
                sparse[(size_t)row * DS + gi] = wv;
            }
            if (i0 == wg) v0 = -FLT_MAX;
            if (i1 == wg) v1 = -FLT_MAX;
        }
    }
}

// ---------------------------------------------------------------------------
// Kernel 4: zero-fill sparse output region
// ---------------------------------------------------------------------------
__global__ void zero_kernel(float4* __restrict__ p, size_t n4)
{
    size_t i = (size_t)blockIdx.x * blockDim.x + threadIdx.x;
    if (i < n4) p[i] = make_float4(0.f, 0.f, 0.f, 0.f);
}

// ---------------------------------------------------------------------------
// Kernel 5: transpose W_dec [768, 12288] -> [12288, 768]
// ---------------------------------------------------------------------------
__global__ void transpose_kernel(const float* __restrict__ W_dec)
{
    __shared__ float t[32][33];
    int s0 = blockIdx.x * 32;
    int d0 = blockIdx.y * 32;
    for (int i = threadIdx.y; i < 32; i += 8)
        t[i][threadIdx.x] = W_dec[(size_t)(d0 + i) * DS + s0 + threadIdx.x];
    __syncthreads();
    for (int i = threadIdx.y; i < 32; i += 8)
        g_wdecT[(size_t)(s0 + i) * DM + d0 + threadIdx.x] = t[threadIdx.x][i];
}

// ---------------------------------------------------------------------------
// Kernel 6: decode — recon[n] = b_dec + sum_j vals[j] * W_decT[idx[j], :]
// 192 threads/row, one float4 column group per thread.
// ---------------------------------------------------------------------------
__global__ __launch_bounds__(192)
void decode_kernel(const float* __restrict__ b_dec, float* __restrict__ recon)
{
    __shared__ float sv[KSEL];
    __shared__ int   si[KSEL];
    const int row = blockIdx.x;
    if (threadIdx.x < KSEL) {
        sv[threadIdx.x] = g_vals[row * KSEL + threadIdx.x];
        si[threadIdx.x] = g_idx [row * KSEL + threadIdx.x];
    }
    __syncthreads();

    const int t = threadIdx.x;   // 0..191
    float4 a = make_float4(0.f, 0.f, 0.f, 0.f);
    #pragma unroll 4
    for (int j = 0; j < KSEL; j++) {
        const float4* wr4 = (const float4*)(g_wdecT + (size_t)si[j] * DM);
        float4 wv = wr4[t];
        float  s  = sv[j];
        a.x += s * wv.x; a.y += s * wv.y; a.z += s * wv.z; a.w += s * wv.w;
    }
    float4 bd = ((const float4*)b_dec)[t];
    a.x += bd.x; a.y += bd.y; a.z += bd.z; a.w += bd.w;
    ((float4*)(recon + (size_t)row * DM))[t] = a;
}

// ---------------------------------------------------------------------------
// launch
// ---------------------------------------------------------------------------
extern "C" void kernel_launch(void* const* d_in, const int* in_sizes, int n_in,
                              void* d_out, int out_size)
{
    const float* x     = (const float*)d_in[0];
    const float* W_enc = (const float*)d_in[1];
    const float* b_enc = (const float*)d_in[2];
    const float* W_dec = (const float*)d_in[3];
    const float* b_dec = (const float*)d_in[4];

    float* recon  = (float*)d_out;
    float* sparse = recon + (size_t)N_ROWS * DM;

    static int smem_set = 0;
    if (!smem_set) {
        cudaFuncSetAttribute(encode_gemm_bf16,
                             cudaFuncAttributeMaxDynamicSharedMemorySize,
                             ENC_SMEM);
        smem_set = 1;
    }

    // bf16 conversions
    {
        __nv_bfloat16* xb; cudaGetSymbolAddress((void**)&xb, g_xb);
        __nv_bfloat16* wb; cudaGetSymbolAddress((void**)&wb, g_wb);
        int nx = N_ROWS * DM;
        int nw = DS * DM;
        convert_kernel<<<(nx / 4 + 255) / 256, 256>>>(x, xb, nx);
        convert_kernel<<<(nw / 4 + 255) / 256, 256>>>(W_enc, wb, nw);
    }

    // independent: W_dec transpose for decode
    transpose_kernel<<<dim3(DS / 32, DM / 32), dim3(32, 8)>>>(W_dec);

    // approx encode (tensor cores, bf16 latents out)
    encode_gemm_bf16<<<dim3(DS / NT, N_ROWS / MT), 256, ENC_SMEM>>>(b_enc);

    // top-48 candidates per row
    topk_cand_kernel<<<N_ROWS, 256>>>();

    // sparse = zeros (must precede refine's scatter)
    size_t n4 = (size_t)N_ROWS * DS / 4;
    zero_kernel<<<(unsigned)((n4 + 255) / 256), 256>>>((float4*)sparse, n4);

    // exact fp32 refine -> top-32 vals/idx + direct scatter
    refine_kernel<<<N_ROWS, 256>>>(x, W_enc, b_enc, sparse);

    // recon
    decode_kernel<<<N_ROWS, 192>>>(b_dec, recon);
}

// round 13
// speedup vs baseline: 1.6391x; 1.6391x over previous
#include <cuda_runtime.h>
#include <cuda_bf16.h>
#include <float.h>
#include <stdint.h>

// ===========================================================================
// TopK SAE — round 12: recombination of measured-good parts only.
//   encode: KT=64 mma.sync, bf16 latents (measured 427us)
//   topk:   round-2 block-argmax algorithm, bf16 loads
//   refine/zero/scatter/decode: round-2/3 verbatim (measured in 1288us run)
// Output layout: d_out = [recon (8192*768) | sparse (8192*12288)] fp32
// ===========================================================================

#define N_ROWS 8192
#define DM     768
#define DS     12288
#define KSEL   32
#define NCAND  48

__device__ __nv_bfloat16  g_latents[(size_t)N_ROWS * DS]; // 201 MB approx scores
__device__ __nv_bfloat16  g_xb[(size_t)N_ROWS * DM];      // bf16 x
__device__ __nv_bfloat16  g_wb[(size_t)DS * DM];          // bf16 W_enc
__device__ float          g_wdecT[(size_t)DS * DM];       // W_dec transposed
__device__ int            g_cidx[N_ROWS * NCAND];
__device__ float          g_vals[N_ROWS * KSEL];
__device__ int            g_idx [N_ROWS * KSEL];

__device__ __forceinline__ uint32_t smem_u32(const void* p) {
    return (uint32_t)__cvta_generic_to_shared(p);
}
__device__ __forceinline__ void cp_async16(uint32_t dst, const void* src) {
    asm volatile("cp.async.cg.shared.global [%0], [%1], 16;\n" :: "r"(dst), "l"(src));
}
__device__ __forceinline__ void ldsm_x4(uint32_t& r0, uint32_t& r1,
                                        uint32_t& r2, uint32_t& r3, uint32_t addr) {
    asm volatile("ldmatrix.sync.aligned.m8n8.x4.shared.b16 {%0,%1,%2,%3}, [%4];"
                 : "=r"(r0), "=r"(r1), "=r"(r2), "=r"(r3) : "r"(addr));
}

// ---------------------------------------------------------------------------
// Kernel 0: fp32 -> bf16 conversion
// ---------------------------------------------------------------------------
__global__ void convert_kernel(const float* __restrict__ src,
                               __nv_bfloat16* __restrict__ dst, int n)
{
    int i = (blockIdx.x * blockDim.x + threadIdx.x) * 4;
    if (i < n) {
        float4 v = *(const float4*)(src + i);
        *(__nv_bfloat162*)(dst + i)     = __floats2bfloat162_rn(v.x, v.y);
        *(__nv_bfloat162*)(dst + i + 2) = __floats2bfloat162_rn(v.z, v.w);
    }
}

// ---------------------------------------------------------------------------
// Kernel 1: bf16 NT-GEMM (mma.sync m16n8k16), CTA tile 128x128, K-chunk 64,
// 2-stage cp.async, 8 warps (4m x 2n), warp tile 32x64. Stores bf16 latents.
// (round-7 version, measured 427us)
// ---------------------------------------------------------------------------
#define MT 128
#define NT 128
#define KT 64
#define NCH (DM / KT)            // 12
#define STG_BYTES (128 * 128)    // 16 KB per operand per stage
#define ENC_SMEM (4 * STG_BYTES) // 64 KB

__device__ __forceinline__ int swzb(int row, int kc) {
    return row * 128 + ((kc ^ (row & 7)) * 16);
}

__global__ __launch_bounds__(256, 2)
void encode_gemm_bf16(const float* __restrict__ b_enc)
{
    extern __shared__ __align__(128) char esm[];
    const uint32_t sb = smem_u32(esm);
    const int tid  = threadIdx.x;
    const int wid  = tid >> 5;
    const int lane = tid & 31;
    const int m0   = blockIdx.y * MT;
    const int n0   = blockIdx.x * NT;
    const int wm   = (wid & 3) * 32;
    const int wn   = (wid >> 2) * 64;

    float acc[2][8][4];
    #pragma unroll
    for (int mt = 0; mt < 2; mt++)
        #pragma unroll
        for (int nt = 0; nt < 8; nt++)
            #pragma unroll
            for (int f = 0; f < 4; f++)
                acc[mt][nt][f] = 0.f;

    auto issue = [&](int st, int kt) {
        const uint32_t Ab = sb + st * STG_BYTES;
        const uint32_t Bb = sb + (2 + st) * STG_BYTES;
        #pragma unroll
        for (int i = 0; i < 4; i++) {
            int u = tid + i * 256;           // 0..1023
            int r = u >> 3, kc = u & 7;
            cp_async16(Ab + swzb(r, kc), g_xb + (size_t)(m0 + r) * DM + kt + kc * 8);
        }
        #pragma unroll
        for (int i = 0; i < 4; i++) {
            int u = tid + i * 256;
            int r = u >> 3, kc = u & 7;
            cp_async16(Bb + swzb(r, kc), g_wb + (size_t)(n0 + r) * DM + kt + kc * 8);
        }
        asm volatile("cp.async.commit_group;\n");
    };

    issue(0, 0);

    for (int it = 0; it < NCH; it++) {
        if (it + 1 < NCH) {
            issue((it + 1) & 1, (it + 1) * KT);
            asm volatile("cp.async.wait_group 1;\n");
        } else {
            asm volatile("cp.async.wait_group 0;\n");
        }
        __syncthreads();

        const uint32_t Ab = sb + (it & 1) * STG_BYTES;
        const uint32_t Bb = sb + (2 + (it & 1)) * STG_BYTES;
        #pragma unroll
        for (int ks = 0; ks < 4; ks++) {          // four k16 steps per chunk
            const int kb = ks * 2;
            uint32_t a[2][4];
            #pragma unroll
            for (int mt = 0; mt < 2; mt++) {
                int row = wm + mt * 16 + (lane & 15);
                int kc  = kb + (lane >> 4);
                ldsm_x4(a[mt][0], a[mt][1], a[mt][2], a[mt][3], Ab + swzb(row, kc));
            }
            uint32_t b[8][2];
            #pragma unroll
            for (int ng = 0; ng < 4; ng++) {
                int row = wn + ng * 16 + (lane & 15);
                int kc  = kb + (lane >> 4);
                uint32_t r0, r1, r2, r3;
                ldsm_x4(r0, r1, r2, r3, Bb + swzb(row, kc));
                b[ng * 2][0]     = r0;
                b[ng * 2 + 1][0] = r1;
                b[ng * 2][1]     = r2;
                b[ng * 2 + 1][1] = r3;
            }
            #pragma unroll
            for (int mt = 0; mt < 2; mt++)
                #pragma unroll
                for (int nt = 0; nt < 8; nt++)
                    asm volatile(
                        "mma.sync.aligned.m16n8k16.row.col.f32.bf16.bf16.f32 "
                        "{%0,%1,%2,%3}, {%4,%5,%6,%7}, {%8,%9}, {%0,%1,%2,%3};"
                        : "+f"(acc[mt][nt][0]), "+f"(acc[mt][nt][1]),
                          "+f"(acc[mt][nt][2]), "+f"(acc[mt][nt][3])
                        : "r"(a[mt][0]), "r"(a[mt][1]), "r"(a[mt][2]), "r"(a[mt][3]),
                          "r"(b[nt][0]), "r"(b[nt][1]));
        }
        __syncthreads();
    }

    // epilogue: + b_enc, store bf16 latents
    #pragma unroll
    for (int mt = 0; mt < 2; mt++) {
        int r0 = m0 + wm + mt * 16 + (lane >> 2);
        #pragma unroll
        for (int nt = 0; nt < 8; nt++) {
            int cg = n0 + wn + nt * 8 + (lane & 3) * 2;
            float2 be = *(const float2*)&b_enc[cg];
            __nv_bfloat162 o0 = __floats2bfloat162_rn(acc[mt][nt][0] + be.x,
                                                      acc[mt][nt][1] + be.y);
            __nv_bfloat162 o1 = __floats2bfloat162_rn(acc[mt][nt][2] + be.x,
                                                      acc[mt][nt][3] + be.y);
            *(__nv_bfloat162*)&g_latents[(size_t)r0 * DS + cg]       = o0;
            *(__nv_bfloat162*)&g_latents[(size_t)(r0 + 8) * DS + cg] = o1;
        }
    }
}

// ---------------------------------------------------------------------------
// Kernel 2: per-row top-48 candidates — round-2 ALGORITHM (block argmax via
// smem + 2 barriers per iter, 32-bit shuffles, winner clears via unrolled
// compare), bf16 uint4 loads. col(j) = (j>>3)*2048 + tid*8 + (j&7).
// ---------------------------------------------------------------------------
#define TPR 48   // elements per thread = DS / 256

__global__ __launch_bounds__(256)
void topk_cand_kernel()
{
    __shared__ float swv[8];
    __shared__ int   swi[8];
    __shared__ int   s_bi;

    const int row = blockIdx.x;
    const int tid = threadIdx.x;
    const uint4* lat4 = (const uint4*)(g_latents + (size_t)row * DS);

    float v[TPR];
    #pragma unroll
    for (int i = 0; i < 6; i++) {
        uint4 c = lat4[tid + i * 256];
        const __nv_bfloat162* h = (const __nv_bfloat162*)&c;
        #pragma unroll
        for (int e2 = 0; e2 < 4; e2++) {
            float2 f = __bfloat1622float2(h[e2]);
            v[i * 8 + e2 * 2]     = f.x;
            v[i * 8 + e2 * 2 + 1] = f.y;
        }
    }

    float lmax = -FLT_MAX;
    int   lj   = 0;
    #pragma unroll
    for (int j = 0; j < TPR; j++)
        if (v[j] > lmax) { lmax = v[j]; lj = j; }

    for (int it = 0; it < NCAND; it++) {
        float wv = lmax;
        int   wg = (lj >> 3) * 2048 + tid * 8 + (lj & 7);
        #pragma unroll
        for (int off = 16; off > 0; off >>= 1) {
            float ov = __shfl_down_sync(0xffffffffu, wv, off);
            int   og = __shfl_down_sync(0xffffffffu, wg, off);
            if (ov > wv) { wv = ov; wg = og; }
        }
        if ((tid & 31) == 0) { swv[tid >> 5] = wv; swi[tid >> 5] = wg; }
        __syncthreads();
        if (tid == 0) {
            float bv = swv[0]; int bg = swi[0];
            #pragma unroll
            for (int w = 1; w < 8; w++)
                if (swv[w] > bv) { bv = swv[w]; bg = swi[w]; }
            g_cidx[row * NCAND + it] = bg;
            s_bi = bg;
        }
        __syncthreads();
        const int bg = s_bi;
        if (((bg >> 3) & 255) == tid) {
            const int jw = ((bg >> 3) >> 8) * 8 + (bg & 7);
            #pragma unroll
            for (int jj = 0; jj < TPR; jj++)
                if (jj == jw) v[jj] = -FLT_MAX;
            lmax = -FLT_MAX; lj = 0;
            #pragma unroll
            for (int jj = 0; jj < TPR; jj++)
                if (v[jj] > lmax) { lmax = v[jj]; lj = jj; }
        }
        __syncthreads();
    }
}

// ---------------------------------------------------------------------------
// Kernel 3: exact fp32 refine (round-2 verbatim) — 48 candidate dots,
// exact top-32 -> g_vals/g_idx.
// ---------------------------------------------------------------------------
__global__ __launch_bounds__(256)
void refine_kernel(const float* __restrict__ x,
                   const float* __restrict__ W_enc,
                   const float* __restrict__ b_enc)
{
    __shared__ float xr[DM];
    __shared__ float cv[NCAND];
    __shared__ int   ci[NCAND];

    const int row  = blockIdx.x;
    const int tid  = threadIdx.x;
    const int wid  = tid >> 5;
    const int lane = tid & 31;

    for (int d = tid; d < DM; d += 256)
        xr[d] = x[(size_t)row * DM + d];
    if (tid < NCAND)
        ci[tid] = g_cidx[row * NCAND + tid];
    __syncthreads();

    for (int j = wid; j < NCAND; j += 8) {
        const int idx = ci[j];
        const float* wr = W_enc + (size_t)idx * DM;
        float s = 0.f;
        #pragma unroll
        for (int d = lane; d < DM; d += 32)
            s += xr[d] * wr[d];
        #pragma unroll
        for (int off = 16; off > 0; off >>= 1)
            s += __shfl_down_sync(0xffffffffu, s, off);
        if (lane == 0) cv[j] = s + b_enc[idx];
    }
    __syncthreads();

    if (wid == 0) {
        float v0 = cv[lane];
        float v1 = (lane < NCAND - 32) ? cv[lane + 32] : -FLT_MAX;
        const int i0 = lane, i1 = lane + 32;
        for (int it = 0; it < KSEL; it++) {
            float m = v0; int mi = i0;
            if (v1 > m) { m = v1; mi = i1; }
            float wv = m; int wg = mi;
            #pragma unroll
            for (int off = 16; off > 0; off >>= 1) {
                float ov = __shfl_down_sync(0xffffffffu, wv, off);
                int   og = __shfl_down_sync(0xffffffffu, wg, off);
                if (ov > wv) { wv = ov; wg = og; }
            }
            wv = __shfl_sync(0xffffffffu, wv, 0);
            wg = __shfl_sync(0xffffffffu, wg, 0);
            if (lane == 0) {
                g_vals[row * KSEL + it] = wv;
                g_idx [row * KSEL + it] = ci[wg];
            }
            if (i0 == wg) v0 = -FLT_MAX;
            if (i1 == wg) v1 = -FLT_MAX;
        }
    }
}

// ---------------------------------------------------------------------------
// Kernel 4a/4b: zero-fill + scatter sparse (round-2 verbatim)
// ---------------------------------------------------------------------------
__global__ void zero_kernel(float4* __restrict__ p, size_t n4)
{
    size_t i = (size_t)blockIdx.x * blockDim.x + threadIdx.x;
    if (i < n4) p[i] = make_float4(0.f, 0.f, 0.f, 0.f);
}

__global__ void scatter_kernel(float* __restrict__ sparse)
{
    int row = blockIdx.x;
    int j   = threadIdx.x;   // 0..31
    sparse[(size_t)row * DS + g_idx[row * KSEL + j]] = g_vals[row * KSEL + j];
}

// ---------------------------------------------------------------------------
// Kernel 5: transpose W_dec [768, 12288] -> [12288, 768]
// ---------------------------------------------------------------------------
__global__ void transpose_kernel(const float* __restrict__ W_dec)
{
    __shared__ float t[32][33];
    int s0 = blockIdx.x * 32;
    int d0 = blockIdx.y * 32;
    for (int i = threadIdx.y; i < 32; i += 8)
        t[i][threadIdx.x] = W_dec[(size_t)(d0 + i) * DS + s0 + threadIdx.x];
    __syncthreads();
    for (int i = threadIdx.y; i < 32; i += 8)
        g_wdecT[(size_t)(s0 + i) * DM + d0 + threadIdx.x] = t[threadIdx.x][i];
}

// ---------------------------------------------------------------------------
// Kernel 6: decode (round-2 verbatim) — recon[n,d] = b_dec[d] + sum_j ...
// ---------------------------------------------------------------------------
__global__ __launch_bounds__(256)
void decode_kernel(const float* __restrict__ b_dec, float* __restrict__ recon)
{
    __shared__ float sv[KSEL];
    __shared__ int   si[KSEL];
    const int row = blockIdx.x;
    if (threadIdx.x < KSEL) {
        sv[threadIdx.x] = g_vals[row * KSEL + threadIdx.x];
        si[threadIdx.x] = g_idx [row * KSEL + threadIdx.x];
    }
    __syncthreads();

    const int d = threadIdx.x;
    float a0 = 0.f, a1 = 0.f, a2 = 0.f;
    #pragma unroll 4
    for (int j = 0; j < KSEL; j++) {
        const float* wr = g_wdecT + (size_t)si[j] * DM;
        float v = sv[j];
        a0 += v * wr[d];
        a1 += v * wr[d + 256];
        a2 += v * wr[d + 512];
    }
    float* out = recon + (size_t)row * DM;
    out[d]       = a0 + b_dec[d];
    out[d + 256] = a1 + b_dec[d + 256];
    out[d + 512] = a2 + b_dec[d + 512];
}

// ---------------------------------------------------------------------------
// launch
// ---------------------------------------------------------------------------
extern "C" void kernel_launch(void* const* d_in, const int* in_sizes, int n_in,
                              void* d_out, int out_size)
{
    const float* x     = (const float*)d_in[0];
    const float* W_enc = (const float*)d_in[1];
    const float* b_enc = (const float*)d_in[2];
    const float* W_dec = (const float*)d_in[3];
    const float* b_dec = (const float*)d_in[4];

    float* recon  = (float*)d_out;
    float* sparse = recon + (size_t)N_ROWS * DM;

    static int smem_set = 0;
    if (!smem_set) {
        cudaFuncSetAttribute(encode_gemm_bf16,
                             cudaFuncAttributeMaxDynamicSharedMemorySize,
                             ENC_SMEM);
        smem_set = 1;
    }

    // bf16 conversions
    {
        __nv_bfloat16* xb; cudaGetSymbolAddress((void**)&xb, g_xb);
        __nv_bfloat16* wb; cudaGetSymbolAddress((void**)&wb, g_wb);
        int nx = N_ROWS * DM;
        int nw = DS * DM;
        convert_kernel<<<(nx / 4 + 255) / 256, 256>>>(x, xb, nx);
        convert_kernel<<<(nw / 4 + 255) / 256, 256>>>(W_enc, wb, nw);
    }

    // independent: W_dec transpose for decode
    transpose_kernel<<<dim3(DS / 32, DM / 32), dim3(32, 8)>>>(W_dec);

    // approx encode (tensor cores, bf16 latents out)
    encode_gemm_bf16<<<dim3(DS / NT, N_ROWS / MT), 256, ENC_SMEM>>>(b_enc);

    // top-48 candidates per row
    topk_cand_kernel<<<N_ROWS, 256>>>();

    // exact fp32 refine -> top-32 vals/idx
    refine_kernel<<<N_ROWS, 256>>>(x, W_enc, b_enc);

    // sparse = zeros; scatter
    size_t n4 = (size_t)N_ROWS * DS / 4;
    zero_kernel<<<(unsigned)((n4 + 255) / 256), 256>>>((float4*)sparse, n4);
    scatter_kernel<<<N_ROWS, KSEL>>>(sparse);

    // recon
    decode_kernel<<<N_ROWS, 192 + 64>>>(b_dec, recon);
}

// round 14
// speedup vs baseline: 2.4880x; 1.5179x over previous
#include <cuda_runtime.h>
#include <cuda_bf16.h>
#include <float.h>
#include <stdint.h>

// ===========================================================================
// TopK SAE — round 13: histogram-select topk (single attributable change
// vs round-13 bench). encode KT=64 mma.sync + bf16 latents (427us measured);
// refine/zero/scatter/decode verbatim from measured runs.
// Output layout: d_out = [recon (8192*768) | sparse (8192*12288)] fp32
// ===========================================================================

#define N_ROWS 8192
#define DM     768
#define DS     12288
#define KSEL   32
#define NCAND  48

__device__ __nv_bfloat16  g_latents[(size_t)N_ROWS * DS]; // 201 MB approx scores
__device__ __nv_bfloat16  g_xb[(size_t)N_ROWS * DM];      // bf16 x
__device__ __nv_bfloat16  g_wb[(size_t)DS * DM];          // bf16 W_enc
__device__ float          g_wdecT[(size_t)DS * DM];       // W_dec transposed
__device__ int            g_cidx[N_ROWS * NCAND];
__device__ float          g_vals[N_ROWS * KSEL];
__device__ int            g_idx [N_ROWS * KSEL];

__device__ __forceinline__ uint32_t smem_u32(const void* p) {
    return (uint32_t)__cvta_generic_to_shared(p);
}
__device__ __forceinline__ void cp_async16(uint32_t dst, const void* src) {
    asm volatile("cp.async.cg.shared.global [%0], [%1], 16;\n" :: "r"(dst), "l"(src));
}
__device__ __forceinline__ void ldsm_x4(uint32_t& r0, uint32_t& r1,
                                        uint32_t& r2, uint32_t& r3, uint32_t addr) {
    asm volatile("ldmatrix.sync.aligned.m8n8.x4.shared.b16 {%0,%1,%2,%3}, [%4];"
                 : "=r"(r0), "=r"(r1), "=r"(r2), "=r"(r3) : "r"(addr));
}

// ---------------------------------------------------------------------------
// Kernel 0: fp32 -> bf16 conversion
// ---------------------------------------------------------------------------
__global__ void convert_kernel(const float* __restrict__ src,
                               __nv_bfloat16* __restrict__ dst, int n)
{
    int i = (blockIdx.x * blockDim.x + threadIdx.x) * 4;
    if (i < n) {
        float4 v = *(const float4*)(src + i);
        *(__nv_bfloat162*)(dst + i)     = __floats2bfloat162_rn(v.x, v.y);
        *(__nv_bfloat162*)(dst + i + 2) = __floats2bfloat162_rn(v.z, v.w);
    }
}

// ---------------------------------------------------------------------------
// Kernel 1: bf16 NT-GEMM (mma.sync m16n8k16), CTA tile 128x128, K-chunk 64,
// 2-stage cp.async, 8 warps (4m x 2n), warp tile 32x64. Stores bf16 latents.
// (measured 427us)
// ---------------------------------------------------------------------------
#define MT 128
#define NT 128
#define KT 64
#define NCH (DM / KT)            // 12
#define STG_BYTES (128 * 128)    // 16 KB per operand per stage
#define ENC_SMEM (4 * STG_BYTES) // 64 KB

__device__ __forceinline__ int swzb(int row, int kc) {
    return row * 128 + ((kc ^ (row & 7)) * 16);
}

__global__ __launch_bounds__(256, 2)
void encode_gemm_bf16(const float* __restrict__ b_enc)
{
    extern __shared__ __align__(128) char esm[];
    const uint32_t sb = smem_u32(esm);
    const int tid  = threadIdx.x;
    const int wid  = tid >> 5;
    const int lane = tid & 31;
    const int m0   = blockIdx.y * MT;
    const int n0   = blockIdx.x * NT;
    const int wm   = (wid & 3) * 32;
    const int wn   = (wid >> 2) * 64;

    float acc[2][8][4];
    #pragma unroll
    for (int mt = 0; mt < 2; mt++)
        #pragma unroll
        for (int nt = 0; nt < 8; nt++)
            #pragma unroll
            for (int f = 0; f < 4; f++)
                acc[mt][nt][f] = 0.f;

    auto issue = [&](int st, int kt) {
        const uint32_t Ab = sb + st * STG_BYTES;
        const uint32_t Bb = sb + (2 + st) * STG_BYTES;
        #pragma unroll
        for (int i = 0; i < 4; i++) {
            int u = tid + i * 256;           // 0..1023
            int r = u >> 3, kc = u & 7;
            cp_async16(Ab + swzb(r, kc), g_xb + (size_t)(m0 + r) * DM + kt + kc * 8);
        }
        #pragma unroll
        for (int i = 0; i < 4; i++) {
            int u = tid + i * 256;
            int r = u >> 3, kc = u & 7;
            cp_async16(Bb + swzb(r, kc), g_wb + (size_t)(n0 + r) * DM + kt + kc * 8);
        }
        asm volatile("cp.async.commit_group;\n");
    };

    issue(0, 0);

    for (int it = 0; it < NCH; it++) {
        if (it + 1 < NCH) {
            issue((it + 1) & 1, (it + 1) * KT);
            asm volatile("cp.async.wait_group 1;\n");
        } else {
            asm volatile("cp.async.wait_group 0;\n");
        }
        __syncthreads();

        const uint32_t Ab = sb + (it & 1) * STG_BYTES;
        const uint32_t Bb = sb + (2 + (it & 1)) * STG_BYTES;
        #pragma unroll
        for (int ks = 0; ks < 4; ks++) {          // four k16 steps per chunk
            const int kb = ks * 2;
            uint32_t a[2][4];
            #pragma unroll
            for (int mt = 0; mt < 2; mt++) {
                int row = wm + mt * 16 + (lane & 15);
                int kc  = kb + (lane >> 4);
                ldsm_x4(a[mt][0], a[mt][1], a[mt][2], a[mt][3], Ab + swzb(row, kc));
            }
            uint32_t b[8][2];
            #pragma unroll
            for (int ng = 0; ng < 4; ng++) {
                int row = wn + ng * 16 + (lane & 15);
                int kc  = kb + (lane >> 4);
                uint32_t r0, r1, r2, r3;
                ldsm_x4(r0, r1, r2, r3, Bb + swzb(row, kc));
                b[ng * 2][0]     = r0;
                b[ng * 2 + 1][0] = r1;
                b[ng * 2][1]     = r2;
                b[ng * 2 + 1][1] = r3;
            }
            #pragma unroll
            for (int mt = 0; mt < 2; mt++)
                #pragma unroll
                for (int nt = 0; nt < 8; nt++)
                    asm volatile(
                        "mma.sync.aligned.m16n8k16.row.col.f32.bf16.bf16.f32 "
                        "{%0,%1,%2,%3}, {%4,%5,%6,%7}, {%8,%9}, {%0,%1,%2,%3};"
                        : "+f"(acc[mt][nt][0]), "+f"(acc[mt][nt][1]),
                          "+f"(acc[mt][nt][2]), "+f"(acc[mt][nt][3])
                        : "r"(a[mt][0]), "r"(a[mt][1]), "r"(a[mt][2]), "r"(a[mt][3]),
                          "r"(b[nt][0]), "r"(b[nt][1]));
        }
        __syncthreads();
    }

    // epilogue: + b_enc, store bf16 latents
    #pragma unroll
    for (int mt = 0; mt < 2; mt++) {
        int r0 = m0 + wm + mt * 16 + (lane >> 2);
        #pragma unroll
        for (int nt = 0; nt < 8; nt++) {
            int cg = n0 + wn + nt * 8 + (lane & 3) * 2;
            float2 be = *(const float2*)&b_enc[cg];
            __nv_bfloat162 o0 = __floats2bfloat162_rn(acc[mt][nt][0] + be.x,
                                                      acc[mt][nt][1] + be.y);
            __nv_bfloat162 o1 = __floats2bfloat162_rn(acc[mt][nt][2] + be.x,
                                                      acc[mt][nt][3] + be.y);
            *(__nv_bfloat162*)&g_latents[(size_t)r0 * DS + cg]       = o0;
            *(__nv_bfloat162*)&g_latents[(size_t)(r0 + 8) * DS + cg] = o1;
        }
    }
}

// ---------------------------------------------------------------------------
// Kernel 2: per-row top-48 candidates via two-level HISTOGRAM selection.
// bf16 keys under order-preserving u16 map; no serial argmax iterations.
//  1) 256-bin hist of high byte -> boundary bin b1 (descending-count cross 48)
//  2) 256-bin hist of low byte within b1 -> exact 16-bit threshold T
//  3) emit cols with key > T (count < 48), fill to 48 from key == T.
// Candidate order is arbitrary; refine re-scores exactly.
// ---------------------------------------------------------------------------
__global__ __launch_bounds__(256)
void topk_cand_kernel()
{
    __shared__ uint32_t h1[256];
    __shared__ uint32_t h2[256];
    __shared__ int      cbuf[NCAND];
    __shared__ int      s_b1, s_c1, s_T, s_cnt;

    const int row  = blockIdx.x;
    const int tid  = threadIdx.x;
    const int lane = tid & 31;

    h1[tid] = 0;
    h2[tid] = 0;
    if (tid == 0) s_cnt = 0;

    // load 48 bf16 keys (order-preserving u16 map, no float convert)
    const uint4* lat4 = (const uint4*)(g_latents + (size_t)row * DS);
    uint32_t key[48];
    #pragma unroll
    for (int i = 0; i < 6; i++) {
        uint4 c = lat4[tid + i * 256];
        uint32_t ws[4] = {c.x, c.y, c.z, c.w};
        #pragma unroll
        for (int q = 0; q < 4; q++) {
            uint32_t lo = ws[q] & 0xFFFFu;
            uint32_t hi = ws[q] >> 16;
            key[i * 8 + q * 2]     = (lo & 0x8000u) ? (~lo & 0xFFFFu) : (lo | 0x8000u);
            key[i * 8 + q * 2 + 1] = (hi & 0x8000u) ? (~hi & 0xFFFFu) : (hi | 0x8000u);
        }
    }
    // col(j) = tid*8 + (j>>3)*2048 + (j&7)
    __syncthreads();

    // pass 1: histogram of high byte
    #pragma unroll
    for (int j = 0; j < 48; j++)
        atomicAdd(&h1[key[j] >> 8], 1u);
    __syncthreads();

    // warp 0: boundary bin b1 + count strictly above it (c1)
    if (tid < 32) {
        uint32_t gs = 0;
        #pragma unroll
        for (int k = 0; k < 8; k++) gs += h1[lane * 8 + k];
        uint32_t incl = gs;
        #pragma unroll
        for (int off = 1; off < 32; off <<= 1) {
            uint32_t t = __shfl_down_sync(0xffffffffu, incl, off);
            if (lane + off < 32) incl += t;
        }
        uint32_t excl = incl - gs;       // count with hi-byte in groups above this lane
        bool cross = (excl < NCAND) && (incl >= NCAND);
        uint32_t bal = __ballot_sync(0xffffffffu, cross);
        int src = __ffs((int)bal) - 1;
        if (lane == src) {
            uint32_t A = excl;
            int b1 = lane * 8;
            for (int b = lane * 8 + 7; b >= lane * 8; b--) {
                uint32_t hb = h1[b];
                if (A + hb >= NCAND) { b1 = b; break; }
                A += hb;
            }
            s_b1 = b1;
            s_c1 = (int)A;
        }
    }
    __syncthreads();
    const uint32_t b1 = (uint32_t)s_b1;
    const uint32_t c1 = (uint32_t)s_c1;

    // pass 2: histogram of low byte among keys with hi == b1
    #pragma unroll
    for (int j = 0; j < 48; j++)
        if ((key[j] >> 8) == b1)
            atomicAdd(&h2[key[j] & 255u], 1u);
    __syncthreads();

    if (tid < 32) {
        uint32_t gs = 0;
        #pragma unroll
        for (int k = 0; k < 8; k++) gs += h2[lane * 8 + k];
        uint32_t incl = gs;
        #pragma unroll
        for (int off = 1; off < 32; off <<= 1) {
            uint32_t t = __shfl_down_sync(0xffffffffu, incl, off);
            if (lane + off < 32) incl += t;
        }
        uint32_t excl = incl - gs;
        bool cross = (c1 + excl < NCAND) && (c1 + incl >= NCAND);
        uint32_t bal = __ballot_sync(0xffffffffu, cross);
        int src = __ffs((int)bal) - 1;
        if (lane == src) {
            uint32_t A = c1 + excl;
            int b2 = lane * 8;
            for (int b = lane * 8 + 7; b >= lane * 8; b--) {
                uint32_t hb = h2[b];
                if (A + hb >= NCAND) { b2 = b; break; }
                A += hb;
            }
            s_T = (int)((b1 << 8) | (uint32_t)b2);
        }
    }
    __syncthreads();
    const uint32_t T = (uint32_t)s_T;

    // collect strictly greater (guaranteed < 48 of them)
    #pragma unroll
    for (int j = 0; j < 48; j++) {
        if (key[j] > T) {
            int pos = atomicAdd(&s_cnt, 1);
            cbuf[pos] = tid * 8 + (j >> 3) * 2048 + (j & 7);
        }
    }
    __syncthreads();
    // fill remaining slots with == T (ties; arbitrary subset is safe)
    #pragma unroll
    for (int j = 0; j < 48; j++) {
        if (key[j] == T) {
            int pos = atomicAdd(&s_cnt, 1);
            if (pos < NCAND)
                cbuf[pos] = tid * 8 + (j >> 3) * 2048 + (j & 7);
        }
    }
    __syncthreads();

    if (tid < NCAND)
        g_cidx[row * NCAND + tid] = cbuf[tid];
}

// ---------------------------------------------------------------------------
// Kernel 3: exact fp32 refine (verbatim) — 48 candidate dots, exact top-32.
// ---------------------------------------------------------------------------
__global__ __launch_bounds__(256)
void refine_kernel(const float* __restrict__ x,
                   const float* __restrict__ W_enc,
                   const float* __restrict__ b_enc)
{
    __shared__ float xr[DM];
    __shared__ float cv[NCAND];
    __shared__ int   ci[NCAND];

    const int row  = blockIdx.x;
    const int tid  = threadIdx.x;
    const int wid  = tid >> 5;
    const int lane = tid & 31;

    for (int d = tid; d < DM; d += 256)
        xr[d] = x[(size_t)row * DM + d];
    if (tid < NCAND)
        ci[tid] = g_cidx[row * NCAND + tid];
    __syncthreads();

    for (int j = wid; j < NCAND; j += 8) {
        const int idx = ci[j];
        const float* wr = W_enc + (size_t)idx * DM;
        float s = 0.f;
        #pragma unroll
        for (int d = lane; d < DM; d += 32)
            s += xr[d] * wr[d];
        #pragma unroll
        for (int off = 16; off > 0; off >>= 1)
            s += __shfl_down_sync(0xffffffffu, s, off);
        if (lane == 0) cv[j] = s + b_enc[idx];
    }
    __syncthreads();

    if (wid == 0) {
        float v0 = cv[lane];
        float v1 = (lane < NCAND - 32) ? cv[lane + 32] : -FLT_MAX;
        const int i0 = lane, i1 = lane + 32;
        for (int it = 0; it < KSEL; it++) {
            float m = v0; int mi = i0;
            if (v1 > m) { m = v1; mi = i1; }
            float wv = m; int wg = mi;
            #pragma unroll
            for (int off = 16; off > 0; off >>= 1) {
                float ov = __shfl_down_sync(0xffffffffu, wv, off);
                int   og = __shfl_down_sync(0xffffffffu, wg, off);
                if (ov > wv) { wv = ov; wg = og; }
            }
            wv = __shfl_sync(0xffffffffu, wv, 0);
            wg = __shfl_sync(0xffffffffu, wg, 0);
            if (lane == 0) {
                g_vals[row * KSEL + it] = wv;
                g_idx [row * KSEL + it] = ci[wg];
            }
            if (i0 == wg) v0 = -FLT_MAX;
            if (i1 == wg) v1 = -FLT_MAX;
        }
    }
}

// ---------------------------------------------------------------------------
// Kernel 4a/4b: zero-fill + scatter sparse (verbatim)
// ---------------------------------------------------------------------------
__global__ void zero_kernel(float4* __restrict__ p, size_t n4)
{
    size_t i = (size_t)blockIdx.x * blockDim.x + threadIdx.x;
    if (i < n4) p[i] = make_float4(0.f, 0.f, 0.f, 0.f);
}

__global__ void scatter_kernel(float* __restrict__ sparse)
{
    int row = blockIdx.x;
    int j   = threadIdx.x;   // 0..31
    sparse[(size_t)row * DS + g_idx[row * KSEL + j]] = g_vals[row * KSEL + j];
}

// ---------------------------------------------------------------------------
// Kernel 5: transpose W_dec [768, 12288] -> [12288, 768]
// ---------------------------------------------------------------------------
__global__ void transpose_kernel(const float* __restrict__ W_dec)
{
    __shared__ float t[32][33];
    int s0 = blockIdx.x * 32;
    int d0 = blockIdx.y * 32;
    for (int i = threadIdx.y; i < 32; i += 8)
        t[i][threadIdx.x] = W_dec[(size_t)(d0 + i) * DS + s0 + threadIdx.x];
    __syncthreads();
    for (int i = threadIdx.y; i < 32; i += 8)
        g_wdecT[(size_t)(s0 + i) * DM + d0 + threadIdx.x] = t[threadIdx.x][i];
}

// ---------------------------------------------------------------------------
// Kernel 6: decode (verbatim) — recon[n,d] = b_dec[d] + sum_j vals*W_decT
// ---------------------------------------------------------------------------
__global__ __launch_bounds__(256)
void decode_kernel(const float* __restrict__ b_dec, float* __restrict__ recon)
{
    __shared__ float sv[KSEL];
    __shared__ int   si[KSEL];
    const int row = blockIdx.x;
    if (threadIdx.x < KSEL) {
        sv[threadIdx.x] = g_vals[row * KSEL + threadIdx.x];
        si[threadIdx.x] = g_idx [row * KSEL + threadIdx.x];
    }
    __syncthreads();

    const int d = threadIdx.x;
    float a0 = 0.f, a1 = 0.f, a2 = 0.f;
    #pragma unroll 4
    for (int j = 0; j < KSEL; j++) {
        const float* wr = g_wdecT + (size_t)si[j] * DM;
        float v = sv[j];
        a0 += v * wr[d];
        a1 += v * wr[d + 256];
        a2 += v * wr[d + 512];
    }
    float* out = recon + (size_t)row * DM;
    out[d]       = a0 + b_dec[d];
    out[d + 256] = a1 + b_dec[d + 256];
    out[d + 512] = a2 + b_dec[d + 512];
}

// ---------------------------------------------------------------------------
// launch
// ---------------------------------------------------------------------------
extern "C" void kernel_launch(void* const* d_in, const int* in_sizes, int n_in,
                              void* d_out, int out_size)
{
    const float* x     = (const float*)d_in[0];
    const float* W_enc = (const float*)d_in[1];
    const float* b_enc = (const float*)d_in[2];
    const float* W_dec = (const float*)d_in[3];
    const float* b_dec = (const float*)d_in[4];

    float* recon  = (float*)d_out;
    float* sparse = recon + (size_t)N_ROWS * DM;

    static int smem_set = 0;
    if (!smem_set) {
        cudaFuncSetAttribute(encode_gemm_bf16,
                             cudaFuncAttributeMaxDynamicSharedMemorySize,
                             ENC_SMEM);
        smem_set = 1;
    }

    // bf16 conversions
    {
        __nv_bfloat16* xb; cudaGetSymbolAddress((void**)&xb, g_xb);
        __nv_bfloat16* wb; cudaGetSymbolAddress((void**)&wb, g_wb);
        int nx = N_ROWS * DM;
        int nw = DS * DM;
        convert_kernel<<<(nx / 4 + 255) / 256, 256>>>(x, xb, nx);
        convert_kernel<<<(nw / 4 + 255) / 256, 256>>>(W_enc, wb, nw);
    }

    // independent: W_dec transpose for decode
    transpose_kernel<<<dim3(DS / 32, DM / 32), dim3(32, 8)>>>(W_dec);

    // approx encode (tensor cores, bf16 latents out)
    encode_gemm_bf16<<<dim3(DS / NT, N_ROWS / MT), 256, ENC_SMEM>>>(b_enc);

    // top-48 candidates per row (histogram selection)
    topk_cand_kernel<<<N_ROWS, 256>>>();

    // exact fp32 refine -> top-32 vals/idx
    refine_kernel<<<N_ROWS, 256>>>(x, W_enc, b_enc);

    // sparse = zeros; scatter
    size_t n4 = (size_t)N_ROWS * DS / 4;
    zero_kernel<<<(unsigned)((n4 + 255) / 256), 256>>>((float4*)sparse, n4);
    scatter_kernel<<<N_ROWS, KSEL>>>(sparse);

    // recon
    decode_kernel<<<N_ROWS, 256>>>(b_dec, recon);
}